// round 5
// baseline (speedup 1.0000x reference)
#include <cuda_runtime.h>
#include <cuda_bf16.h>
#include <cstdint>

// ---------------------------------------------------------------------------
// ShufflerAttention — fully fused per-window kernel (round 5).
// Shapes: B=4, NB=64, T=512, C=256, H=8, HD=32, FW=TW=8
// 2048 windows x 64 tokens. Window token (b,n,t) gathers from and scatters to
// the SAME global position (b, perm_n[b,n], perm_t[b,t]), so the whole op
// after LN is local to one 64-token window -> one CTA does everything:
//   LN+gather -> QKV GEMM -> attention -> proj GEMM -> +residual scatter.
// Intermediates (Xw 33KB, QKV 99KB, O reuses Xw) live in SMEM; weights stream
// from L2 (0.5MB, shared by all CTAs). DRAM traffic ~= inpt(2x) + out only.
// ---------------------------------------------------------------------------

#define NWIN 2048
static constexpr float SCALE = 0.17677669529663689f;  // 32^-0.5

// Only weights persist in global scratch now.
__device__ __align__(128) __nv_bfloat16 g_Wqkv[768 * 256];  // Wq*SCALE | Wk | Wv  (row-major [n][k])
__device__ __align__(128) __nv_bfloat16 g_Wp  [256 * 256];

// SMEM layout (bytes): strides in bf16 elements chosen so row stride mod 32
// words == 4 -> all 8-row ldmatrix phases hit distinct bank groups.
#define XS_STRIDE   264     // 64 x 264 bf16  (Xw, later reused as O)
#define QKV_STRIDE  776     // 64 x 776 bf16  (q | k | v per row)
#define WT_STRIDE   264     // 128 x 264 bf16 (weight tile)
#define XS_OFF      0
#define QKV_OFF     33792   // 64*264*2
#define WT_OFF      133120  // QKV_OFF + 64*776*2
#define SMEM_BYTES  200704  // WT_OFF + 128*264*2

// ----------------------------- PTX helpers --------------------------------
__device__ __forceinline__ void mma_bf16(float c[4], const uint32_t a[4], const uint32_t b[2]) {
    asm volatile(
        "mma.sync.aligned.m16n8k16.row.col.f32.bf16.bf16.f32 "
        "{%0,%1,%2,%3}, {%4,%5,%6,%7}, {%8,%9}, {%0,%1,%2,%3};\n"
        : "+f"(c[0]), "+f"(c[1]), "+f"(c[2]), "+f"(c[3])
        : "r"(a[0]), "r"(a[1]), "r"(a[2]), "r"(a[3]), "r"(b[0]), "r"(b[1]));
}
__device__ __forceinline__ uint32_t pack_bf16(float lo, float hi) {
    __nv_bfloat162 t = __floats2bfloat162_rn(lo, hi);
    return *reinterpret_cast<uint32_t*>(&t);
}
__device__ __forceinline__ uint32_t smem_u32(const void* p) {
    return (uint32_t)__cvta_generic_to_shared(p);
}
__device__ __forceinline__ void cp_async16(uint32_t dst, const void* src) {
    asm volatile("cp.async.cg.shared.global [%0], [%1], 16;\n" :: "r"(dst), "l"(src));
}
__device__ __forceinline__ void cp_commit() { asm volatile("cp.async.commit_group;\n"); }
__device__ __forceinline__ void cp_wait0()  { asm volatile("cp.async.wait_group 0;\n"); }
__device__ __forceinline__ void ldmx4(uint32_t& r0, uint32_t& r1, uint32_t& r2, uint32_t& r3,
                                      uint32_t addr) {
    asm volatile("ldmatrix.sync.aligned.m8n8.x4.shared.b16 {%0,%1,%2,%3}, [%4];\n"
                 : "=r"(r0), "=r"(r1), "=r"(r2), "=r"(r3) : "r"(addr));
}
__device__ __forceinline__ void ldmx4t(uint32_t& r0, uint32_t& r1, uint32_t& r2, uint32_t& r3,
                                       uint32_t addr) {
    asm volatile("ldmatrix.sync.aligned.m8n8.x4.trans.shared.b16 {%0,%1,%2,%3}, [%4];\n"
                 : "=r"(r0), "=r"(r1), "=r"(r2), "=r"(r3) : "r"(addr));
}

__device__ __forceinline__ float qkv_bias(int n, const float* bq, const float* bk, const float* bv) {
    if (n < 256) return __ldg(bq + n) * SCALE;
    if (n < 512) return __ldg(bk + n - 256);
    return __ldg(bv + n - 512);
}

// ---------------------------------------------------------------------------
// K0: weight convert to bf16 (fold SCALE into Wq rows)
// ---------------------------------------------------------------------------
__global__ void __launch_bounds__(256) k_wconv(const float* __restrict__ Wq,
                                               const float* __restrict__ Wk,
                                               const float* __restrict__ Wv,
                                               const float* __restrict__ Wp) {
    int j = blockIdx.x * 256 + threadIdx.x;
    g_Wqkv[j]          = __float2bfloat16(Wq[j] * SCALE);
    g_Wqkv[65536 + j]  = __float2bfloat16(Wk[j]);
    g_Wqkv[131072 + j] = __float2bfloat16(Wv[j]);
    g_Wp[j]            = __float2bfloat16(Wp[j]);
}

// ---------------------------------------------------------------------------
// K1: the fused per-window kernel. 512 threads = 16 warps, 1 CTA per window.
// ---------------------------------------------------------------------------
__global__ void __launch_bounds__(512, 1) k_fused(const float* __restrict__ inpt,
                                                  const int*   __restrict__ perm_n,
                                                  const int*   __restrict__ perm_t,
                                                  const float* __restrict__ ln_g,
                                                  const float* __restrict__ ln_b,
                                                  const float* __restrict__ bq,
                                                  const float* __restrict__ bk,
                                                  const float* __restrict__ bv,
                                                  const float* __restrict__ bp,
                                                  float* __restrict__ out) {
    extern __shared__ __align__(16) char smem[];
    __nv_bfloat16* Xs   = (__nv_bfloat16*)(smem + XS_OFF);    // [64][264]; later O
    __nv_bfloat16* QKVs = (__nv_bfloat16*)(smem + QKV_OFF);   // [64][776]
    __nv_bfloat16* Wt   = (__nv_bfloat16*)(smem + WT_OFF);    // [128][264]

    const int w = blockIdx.x;
    const int bat = w >> 9, wi = (w >> 6) & 7, wj = w & 63;
    const int tid = threadIdx.x;
    const int wid = tid >> 5, lane = tid & 31;

    // fragment lane decompositions (identical to the proven R4 kernels)
    const int g = lane >> 2, q = lane & 3;
    const int frRow = lane & 15, frCol = (lane >> 4) * 8;
    const int bRow = ((lane >> 4) << 3) + (lane & 7);
    const int bCol = ((lane >> 3) & 1) * 8;

    // ---------------- Stage 1: LN + permuted gather into Xs -----------------
    {
        const int r = tid >> 3;                 // window row 0..63
        const int c0 = (tid & 7) * 32;          // 32 channels per thread
        const int fw = r >> 3, tw = r & 7;
        const int gn = __ldg(perm_n + bat * 64 + wi * 8 + fw);
        const int gt = __ldg(perm_t + bat * 512 + wj * 8 + tw);
        const float* src = inpt + ((size_t)((bat * 64 + gn) * 512 + gt)) * 256 + c0;

        float v[32];
        #pragma unroll
        for (int p = 0; p < 8; ++p) *(float4*)(v + p * 4) = *(const float4*)(src + p * 4);

        float s = 0.f, sq = 0.f;
        #pragma unroll
        for (int p = 0; p < 32; ++p) { s += v[p]; sq += v[p] * v[p]; }
        #pragma unroll
        for (int off = 4; off; off >>= 1) {     // reduce over 8-lane row group
            s  += __shfl_xor_sync(0xffffffffu, s,  off);
            sq += __shfl_xor_sync(0xffffffffu, sq, off);
        }
        const float mean = s * (1.0f / 256.0f);
        const float var  = sq * (1.0f / 256.0f) - mean * mean;
        const float rinv = rsqrtf(var + 1e-5f);

        __nv_bfloat162* dst = (__nv_bfloat162*)(Xs + r * XS_STRIDE + c0);
        #pragma unroll
        for (int p = 0; p < 16; ++p) {
            const float gg0 = __ldg(ln_g + c0 + 2 * p), gg1 = __ldg(ln_g + c0 + 2 * p + 1);
            const float bb0 = __ldg(ln_b + c0 + 2 * p), bb1 = __ldg(ln_b + c0 + 2 * p + 1);
            dst[p] = __floats2bfloat162_rn((v[2 * p] - mean) * rinv * gg0 + bb0,
                                           (v[2 * p + 1] - mean) * rinv * gg1 + bb1);
        }
    }
    __syncthreads();

    // ---------------- Stage 2: QKV GEMM (64 x 768 x 256), 6 n-chunks --------
    // warp layout per chunk: 4(m) x 4(n); warp tile 16 x 32.
    const int wm = wid & 3, wn = wid >> 2;
    for (int nc = 0; nc < 6; ++nc) {
        // stream weight tile rows [nc*128, +128) into Wt
        #pragma unroll
        for (int it = 0; it < 8; ++it) {
            const int chunk = tid + it * 512;          // 0..4095
            const int row = chunk >> 5, c8 = (chunk & 31) * 8;
            cp_async16(smem_u32(Wt + row * WT_STRIDE + c8),
                       g_Wqkv + (size_t)(nc * 128 + row) * 256 + c8);
        }
        cp_commit();
        cp_wait0();
        __syncthreads();

        float acc[4][4];
        #pragma unroll
        for (int a = 0; a < 4; ++a)
            #pragma unroll
            for (int c = 0; c < 4; ++c) acc[a][c] = 0.f;

        #pragma unroll
        for (int kk = 0; kk < 16; ++kk) {
            const int k0 = kk * 16;
            uint32_t a[4], bfr[4][2];
            ldmx4(a[0], a[1], a[2], a[3],
                  smem_u32(Xs + (wm * 16 + frRow) * XS_STRIDE + k0 + frCol));
            #pragma unroll
            for (int nip = 0; nip < 2; ++nip)
                ldmx4(bfr[2 * nip][0], bfr[2 * nip][1], bfr[2 * nip + 1][0], bfr[2 * nip + 1][1],
                      smem_u32(Wt + (wn * 32 + nip * 16 + bRow) * WT_STRIDE + k0 + bCol));
            #pragma unroll
            for (int ni = 0; ni < 4; ++ni) mma_bf16(acc[ni], a, bfr[ni]);
        }

        // epilogue -> QKVs (bias added)
        #pragma unroll
        for (int ni = 0; ni < 4; ++ni) {
            const int n0 = nc * 128 + wn * 32 + ni * 8 + q * 2;
            const float b0 = qkv_bias(n0, bq, bk, bv);
            const float b1 = qkv_bias(n0 + 1, bq, bk, bv);
            const int r0 = wm * 16 + g;
            *(uint32_t*)(QKVs + r0 * QKV_STRIDE + n0)       = pack_bf16(acc[ni][0] + b0, acc[ni][1] + b1);
            *(uint32_t*)(QKVs + (r0 + 8) * QKV_STRIDE + n0) = pack_bf16(acc[ni][2] + b0, acc[ni][3] + b1);
        }
        __syncthreads();   // Wt reads done + QKVs visible before next chunk
    }

    // ---------------- Stage 3: attention (2 head passes, 16-row warps) ------
    // warp unit: head h = (wid>>2) + hp*4, rows m0 = (wid&3)*16.
    for (int hp = 0; hp < 2; ++hp) {
        const int h = (wid >> 2) + hp * 4;
        const int m0 = (wid & 3) * 16;
        const int qcol = h * 32, kcol = 256 + h * 32, vcol = 512 + h * 32;

        float s[8][4];
        #pragma unroll
        for (int ni = 0; ni < 8; ++ni) { s[ni][0] = s[ni][1] = s[ni][2] = s[ni][3] = 0.f; }

        #pragma unroll
        for (int ks = 0; ks < 2; ++ks) {
            const int k0 = ks * 16;
            uint32_t a[4];
            ldmx4(a[0], a[1], a[2], a[3],
                  smem_u32(QKVs + (m0 + frRow) * QKV_STRIDE + qcol + k0 + frCol));
            #pragma unroll
            for (int nip = 0; nip < 4; ++nip) {
                uint32_t bb[4];
                ldmx4(bb[0], bb[1], bb[2], bb[3],
                      smem_u32(QKVs + (nip * 16 + bRow) * QKV_STRIDE + kcol + k0 + bCol));
                mma_bf16(s[2 * nip],     a, bb);
                mma_bf16(s[2 * nip + 1], a, bb + 2);
            }
        }

        // softmax over 64 cols; rows (m0+g) -> s[*][0..1], (m0+g+8) -> s[*][2..3]
        float mx0 = -1e30f, mx1 = -1e30f;
        #pragma unroll
        for (int ni = 0; ni < 8; ++ni) {
            mx0 = fmaxf(mx0, fmaxf(s[ni][0], s[ni][1]));
            mx1 = fmaxf(mx1, fmaxf(s[ni][2], s[ni][3]));
        }
        mx0 = fmaxf(mx0, __shfl_xor_sync(0xffffffffu, mx0, 1));
        mx0 = fmaxf(mx0, __shfl_xor_sync(0xffffffffu, mx0, 2));
        mx1 = fmaxf(mx1, __shfl_xor_sync(0xffffffffu, mx1, 1));
        mx1 = fmaxf(mx1, __shfl_xor_sync(0xffffffffu, mx1, 2));
        float sum0 = 0.f, sum1 = 0.f;
        #pragma unroll
        for (int ni = 0; ni < 8; ++ni) {
            s[ni][0] = __expf(s[ni][0] - mx0);
            s[ni][1] = __expf(s[ni][1] - mx0);
            s[ni][2] = __expf(s[ni][2] - mx1);
            s[ni][3] = __expf(s[ni][3] - mx1);
            sum0 += s[ni][0] + s[ni][1];
            sum1 += s[ni][2] + s[ni][3];
        }
        sum0 += __shfl_xor_sync(0xffffffffu, sum0, 1);
        sum0 += __shfl_xor_sync(0xffffffffu, sum0, 2);
        sum1 += __shfl_xor_sync(0xffffffffu, sum1, 1);
        sum1 += __shfl_xor_sync(0xffffffffu, sum1, 2);
        const float inv0 = 1.f / sum0, inv1 = 1.f / sum1;

        float o[4][4];
        #pragma unroll
        for (int ni = 0; ni < 4; ++ni) { o[ni][0] = o[ni][1] = o[ni][2] = o[ni][3] = 0.f; }

        #pragma unroll
        for (int kt = 0; kt < 4; ++kt) {
            uint32_t a[4];
            a[0] = pack_bf16(s[2 * kt][0],     s[2 * kt][1]);
            a[1] = pack_bf16(s[2 * kt][2],     s[2 * kt][3]);
            a[2] = pack_bf16(s[2 * kt + 1][0], s[2 * kt + 1][1]);
            a[3] = pack_bf16(s[2 * kt + 1][2], s[2 * kt + 1][3]);
            const int t0 = kt * 16;
            #pragma unroll
            for (int nip = 0; nip < 2; ++nip) {
                uint32_t bb[4];
                ldmx4t(bb[0], bb[1], bb[2], bb[3],
                       smem_u32(QKVs + (t0 + frRow) * QKV_STRIDE + vcol + nip * 16 + frCol));
                mma_bf16(o[2 * nip],     a, bb);
                mma_bf16(o[2 * nip + 1], a, bb + 2);
            }
        }

        // write O into the (now dead) Xs region
        #pragma unroll
        for (int ni = 0; ni < 4; ++ni) {
            const int d0 = h * 32 + ni * 8 + q * 2;
            *(uint32_t*)(Xs + (m0 + g) * XS_STRIDE + d0)     = pack_bf16(o[ni][0] * inv0, o[ni][1] * inv0);
            *(uint32_t*)(Xs + (m0 + g + 8) * XS_STRIDE + d0) = pack_bf16(o[ni][2] * inv1, o[ni][3] * inv1);
        }
    }
    __syncthreads();   // O (in Xs) visible to all warps

    // ---------------- Stage 4: projection + bias + residual + scatter -------
    for (int nc = 0; nc < 2; ++nc) {
        #pragma unroll
        for (int it = 0; it < 8; ++it) {
            const int chunk = tid + it * 512;
            const int row = chunk >> 5, c8 = (chunk & 31) * 8;
            cp_async16(smem_u32(Wt + row * WT_STRIDE + c8),
                       g_Wp + (size_t)(nc * 128 + row) * 256 + c8);
        }
        cp_commit();
        cp_wait0();
        __syncthreads();

        float acc[4][4];
        #pragma unroll
        for (int a = 0; a < 4; ++a)
            #pragma unroll
            for (int c = 0; c < 4; ++c) acc[a][c] = 0.f;

        #pragma unroll
        for (int kk = 0; kk < 16; ++kk) {
            const int k0 = kk * 16;
            uint32_t a[4], bfr[4][2];
            ldmx4(a[0], a[1], a[2], a[3],
                  smem_u32(Xs + (wm * 16 + frRow) * XS_STRIDE + k0 + frCol));
            #pragma unroll
            for (int nip = 0; nip < 2; ++nip)
                ldmx4(bfr[2 * nip][0], bfr[2 * nip][1], bfr[2 * nip + 1][0], bfr[2 * nip + 1][1],
                      smem_u32(Wt + (wn * 32 + nip * 16 + bRow) * WT_STRIDE + k0 + bCol));
            #pragma unroll
            for (int ni = 0; ni < 4; ++ni) mma_bf16(acc[ni], a, bfr[ni]);
        }

        // epilogue: residual + scatter to the original gathered position
        size_t gbase[2];
        #pragma unroll
        for (int t = 0; t < 2; ++t) {
            const int r = wm * 16 + g + t * 8;          // window row
            const int fw = r >> 3, tw = r & 7;
            const int gn = __ldg(perm_n + bat * 64 + wi * 8 + fw);
            const int gt = __ldg(perm_t + bat * 512 + wj * 8 + tw);
            gbase[t] = (size_t)((bat * 64 + gn) * 512 + gt) * 256;
        }
        #pragma unroll
        for (int ni = 0; ni < 4; ++ni) {
            const int n0 = nc * 128 + wn * 32 + ni * 8 + q * 2;
            const float bp0 = __ldg(bp + n0), bp1 = __ldg(bp + n0 + 1);
            float2 r0v = *(const float2*)(inpt + gbase[0] + n0);
            float2 r1v = *(const float2*)(inpt + gbase[1] + n0);
            *(float2*)(out + gbase[0] + n0) =
                make_float2(r0v.x + acc[ni][0] + bp0, r0v.y + acc[ni][1] + bp1);
            *(float2*)(out + gbase[1] + n0) =
                make_float2(r1v.x + acc[ni][2] + bp0, r1v.y + acc[ni][3] + bp1);
        }
        __syncthreads();   // Wt reads done before next chunk reload
    }
}

// ---------------------------------------------------------------------------
// Launch
// ---------------------------------------------------------------------------
extern "C" void kernel_launch(void* const* d_in, const int* in_sizes, int n_in,
                              void* d_out, int out_size) {
    const float* inpt   = (const float*)d_in[0];
    const int*   perm_n = (const int*)  d_in[1];
    const int*   perm_t = (const int*)  d_in[2];
    const float* ln_g   = (const float*)d_in[3];
    const float* ln_b   = (const float*)d_in[4];
    const float* Wq     = (const float*)d_in[5];
    const float* bq     = (const float*)d_in[6];
    const float* Wk     = (const float*)d_in[7];
    const float* bk     = (const float*)d_in[8];
    const float* Wv     = (const float*)d_in[9];
    const float* bv     = (const float*)d_in[10];
    const float* Wp     = (const float*)d_in[11];
    const float* bp     = (const float*)d_in[12];
    float* out = (float*)d_out;

    cudaFuncSetAttribute(k_fused, cudaFuncAttributeMaxDynamicSharedMemorySize, SMEM_BYTES);

    k_wconv<<<256, 256>>>(Wq, Wk, Wv, Wp);
    k_fused<<<NWIN, 512, SMEM_BYTES>>>(inpt, perm_n, perm_t, ln_g, ln_b,
                                       bq, bk, bv, bp, out);
}